// round 8
// baseline (speedup 1.0000x reference)
#include <cuda_runtime.h>

// Problem constants
#define BQ    8192
#define NSUB  16
#define KC    1024
#define EDIM  16
#define DEPTHQ 3
#define DIMQ  256

// Output layout: [loss(1), z_q_out(B*256), onehot(B*16*1024), idx(B*16)]
#define OFF_LOSS   ((size_t)0)
#define OFF_ZQ     ((size_t)1)
#define OFF_ONEHOT ((size_t)(1 + BQ * DIMQ))
#define OFF_IDX    ((size_t)(OFF_ONEHOT + (size_t)BQ * NSUB * KC))

__device__ float g_P[(size_t)NSUB * KC * DIMQ];
__device__ int   g_idx[(size_t)BQ * NSUB * DEPTHQ];

// ---------------- packed f32x2 helpers ----------------
__device__ __forceinline__ unsigned long long pack2(float a, float b) {
    unsigned long long r;
    asm("mov.b64 %0, {%1,%2};" : "=l"(r) : "f"(a), "f"(b));
    return r;
}
__device__ __forceinline__ void fma2(unsigned long long& d, unsigned long long a, unsigned long long b) {
    asm("fma.rn.f32x2 %0, %1, %2, %0;" : "+l"(d) : "l"(a), "l"(b));
}
__device__ __forceinline__ unsigned long long fma2v(unsigned long long a, unsigned long long b, unsigned long long c) {
    unsigned long long r;
    asm("fma.rn.f32x2 %0, %1, %2, %3;" : "=l"(r) : "l"(a), "l"(b), "l"(c));
    return r;
}
__device__ __forceinline__ unsigned long long add2(unsigned long long a, unsigned long long b) {
    unsigned long long r;
    asm("add.rn.f32x2 %0, %1, %2;" : "=l"(r) : "l"(a), "l"(b));
    return r;
}
__device__ __forceinline__ void unpack2(unsigned long long v, float& lo, float& hi) {
    asm("mov.b64 {%0,%1}, %2;" : "=f"(lo), "=f"(hi) : "l"(v));
}
__device__ __forceinline__ unsigned long long umin64(unsigned long long a, unsigned long long b) {
    return a < b ? a : b;
}
// Candidate key: (bits(d) << 32) | k with d = sqrt(max(s,0)) >= 0.
// uint order == float order for non-negative floats; equal d -> lower k wins.
// This is EXACTLY jnp.argmin over d = sqrt(max(s,0)) with first-index ties.
__device__ __forceinline__ unsigned long long cand64(float s, unsigned int k) {
    float dv = sqrtf(fmaxf(s, 0.0f));
    return ((unsigned long long)__float_as_uint(dv) << 32) | (unsigned long long)k;
}

// ---------------- kernel 1: P precompute (+ zero loss slot) ----------------
__global__ void compute_P_kernel(const float* __restrict__ emb,
                                 const float* __restrict__ W,
                                 float* __restrict__ out) {
    if (blockIdx.x == 0 && threadIdx.x == 0) out[OFF_LOSS] = 0.0f;

    const int n  = blockIdx.x >> 6;
    const int k0 = (blockIdx.x & 63) * 16;
    const int j  = threadIdx.x;

    __shared__ float se[16 * EDIM];
    se[j] = emb[((size_t)n * KC + k0) * EDIM + j];

    float w[16];
#pragma unroll
    for (int i = 0; i < 16; i++) w[i] = W[(size_t)(n * 16 + i) * DIMQ + j];
    __syncthreads();

#pragma unroll
    for (int kk = 0; kk < 16; kk++) {
        float acc = 0.0f;
#pragma unroll
        for (int i = 0; i < 16; i++) acc = fmaf(se[kk * EDIM + i], w[i], acc);
        g_P[((size_t)n * KC + (k0 + kk)) * DIMQ + j] = acc;
    }
}

// ---------------- kernel 2: VQ search — branch-free u64-argmin scan ----------------
// grid (16 row-tiles of 512 rows, 16 n), 256 threads, 2 rows/thread, 2 blocks/SM.
#define NKP (KC / 2)
#define VQ_SMEM ((size_t)(NKP * EDIM * 8 + NKP * 8))

__global__ void __launch_bounds__(256, 2)
vq_kernel(const float* __restrict__ z,
          const float* __restrict__ emb,
          float* __restrict__ out) {
    extern __shared__ unsigned long long sm[];
    unsigned long long* pc = sm;                                 // pc[kp*16 + i] = (e[2kp][i], e[2kp+1][i])
    unsigned long long* s_esq = sm + (size_t)NKP * EDIM;         // (esq[2kp], esq[2kp+1])

    const float* pcf = (const float*)pc;  // e[k][i] at pcf[((k>>1)*16 + i)*2 + (k&1)]

    const int n = blockIdx.y;
    const int rowbase = blockIdx.x * 512;
    const int tid = threadIdx.x;

    // Build paired codebook + esq (sequential fmaf chain per code — matches ref)
    for (int kp = tid; kp < NKP; kp += 256) {
        const float* e0 = emb + ((size_t)n * KC + 2 * kp) * EDIM;
        const float* e1 = e0 + EDIM;
        float esq0 = 0.0f, esq1 = 0.0f;
        unsigned long long* m = pc + (size_t)kp * EDIM;
#pragma unroll
        for (int i = 0; i < 16; i++) {
            float v0 = __ldg(e0 + i);
            float v1 = __ldg(e1 + i);
            esq0 = fmaf(v0, v0, esq0);
            esq1 = fmaf(v1, v1, esq1);
            m[i] = pack2(v0, v1);
        }
        s_esq[kp] = pack2(esq0, esq1);
    }
    __syncthreads();

    // Two rows per thread: A = rowbase+tid, B = rowbase+256+tid.
    const int bA = rowbase + tid;
    const int bB = rowbase + 256 + tid;
    unsigned long long zdA[16], zdB[16];
    unsigned long long zsqA2, zsqB2;
    {
        const float* zA = z + (size_t)bA * DIMQ + n * EDIM;
        const float* zB = z + (size_t)bB * DIMQ + n * EDIM;
        float sA = 0.0f, sB = 0.0f;
#pragma unroll
        for (int i = 0; i < 16; i++) {
            float a = zA[i], b = zB[i];
            zdA[i] = pack2(a, a);
            zdB[i] = pack2(b, b);
            sA = fmaf(a, a, sA);
            sB = fmaf(b, b, sB);
        }
        zsqA2 = pack2(sA, sA);
        zsqB2 = pack2(sB, sB);
    }

    const unsigned long long NEG2 = 0xC0000000C0000000ull;  // (-2.f, -2.f)

    int bkA_last = 0, bkB_last = 0;

    for (int d = 0; d < DEPTHQ; d++) {
        // Onehot zero-fill, chunk d (indices-independent; overlaps DRAM with scan)
        {
            const int r0 = d * 171;
            const int r1 = (d == 2) ? 512 : (r0 + 171);
            for (int rl = r0; rl < r1; rl++) {
                float* dst = out + OFF_ONEHOT + ((size_t)(rowbase + rl) * NSUB + n) * KC;
                dst[tid]       = 0.0f;
                dst[tid + 256] = 0.0f;
                dst[tid + 512] = 0.0f;
                dst[tid + 768] = 0.0f;
            }
        }

        unsigned long long bestA = 0xFFFFFFFFFFFFFFFFull;
        unsigned long long bestB = 0xFFFFFFFFFFFFFFFFull;

        // Two kp (= 4 codes) per iteration: 4 independent 16-deep FMA chains
        // per thread; body is branch-free so ptxas can pipeline LDS freely.
#pragma unroll 1
        for (int kp2 = 0; kp2 < NKP / 2; ++kp2) {
            const ulonglong2* mv0 = (const ulonglong2*)(pc + (size_t)(2 * kp2) * EDIM);
            const ulonglong2* mv1 = mv0 + 8;
            const unsigned long long es0 = s_esq[2 * kp2];
            const unsigned long long es1 = s_esq[2 * kp2 + 1];

            unsigned long long aA0 = 0ull, aB0 = 0ull, aA1 = 0ull, aB1 = 0ull;
            // 4 staged sub-chunks (peak m-regs 16). Per chain, sequential
            // i = 0..15 — bit-matches the scalar fmaf chain.
#pragma unroll
            for (int c = 0; c < 4; c++) {
                ulonglong2 p0 = mv0[2 * c], q0 = mv0[2 * c + 1];
                ulonglong2 p1 = mv1[2 * c], q1 = mv1[2 * c + 1];
                const int i = 4 * c;
                fma2(aA0, zdA[i + 0], p0.x); fma2(aB0, zdB[i + 0], p0.x);
                fma2(aA1, zdA[i + 0], p1.x); fma2(aB1, zdB[i + 0], p1.x);
                fma2(aA0, zdA[i + 1], p0.y); fma2(aB0, zdB[i + 1], p0.y);
                fma2(aA1, zdA[i + 1], p1.y); fma2(aB1, zdB[i + 1], p1.y);
                fma2(aA0, zdA[i + 2], q0.x); fma2(aB0, zdB[i + 2], q0.x);
                fma2(aA1, zdA[i + 2], q1.x); fma2(aB1, zdB[i + 2], q1.x);
                fma2(aA0, zdA[i + 3], q0.y); fma2(aB0, zdB[i + 3], q0.y);
                fma2(aA1, zdA[i + 3], q1.y); fma2(aB1, zdB[i + 3], q1.y);
            }

            // per lane: s = fmaf(-2, c, zsq) + es  (bit-equal to zsq - 2c, then +es)
            unsigned long long sA02 = add2(fma2v(aA0, NEG2, zsqA2), es0);
            unsigned long long sB02 = add2(fma2v(aB0, NEG2, zsqB2), es0);
            unsigned long long sA12 = add2(fma2v(aA1, NEG2, zsqA2), es1);
            unsigned long long sB12 = add2(fma2v(aB1, NEG2, zsqB2), es1);

            float sA0l, sA0h, sA1l, sA1h, sB0l, sB0h, sB1l, sB1h;
            unpack2(sA02, sA0l, sA0h);
            unpack2(sB02, sB0l, sB0h);
            unpack2(sA12, sA1l, sA1h);
            unpack2(sB12, sB1l, sB1h);

            // Branch-free argmin via u64 keys (d-bits, k); min-trees, no serial
            // FSETP chain. Ascending k encoded in low bits preserves the
            // reference's first-index tie-break exactly.
            const unsigned int kb = 4u * (unsigned int)kp2;
            unsigned long long cA = umin64(umin64(cand64(sA0l, kb),     cand64(sA0h, kb + 1)),
                                           umin64(cand64(sA1l, kb + 2), cand64(sA1h, kb + 3)));
            unsigned long long cB = umin64(umin64(cand64(sB0l, kb),     cand64(sB0h, kb + 1)),
                                           umin64(cand64(sB1l, kb + 2), cand64(sB1h, kb + 3)));
            bestA = umin64(bestA, cA);
            bestB = umin64(bestB, cB);
        }

        const int bkA = (int)(unsigned int)bestA;
        const int bkB = (int)(unsigned int)bestB;

        // Residual update (one fp32 sub per component, matching ref), zsq refresh
        {
            const size_t baseA = ((size_t)(bkA >> 1) * EDIM) * 2 + (bkA & 1);
            const size_t baseB = ((size_t)(bkB >> 1) * EDIM) * 2 + (bkB & 1);
            float sA = 0.0f, sB = 0.0f;
#pragma unroll
            for (int i = 0; i < 16; i++) {
                float a, dummy, b;
                unpack2(zdA[i], a, dummy);
                unpack2(zdB[i], b, dummy);
                a = a - pcf[baseA + 2 * i];
                b = b - pcf[baseB + 2 * i];
                sA = fmaf(a, a, sA);
                sB = fmaf(b, b, sB);
                zdA[i] = pack2(a, a);
                zdB[i] = pack2(b, b);
            }
            zsqA2 = pack2(sA, sA);
            zsqB2 = pack2(sB, sB);
        }

        g_idx[((size_t)bA * NSUB + n) * DEPTHQ + d] = bkA;
        g_idx[((size_t)bB * NSUB + n) * DEPTHQ + d] = bkB;
        if (d == DEPTHQ - 1) {
            bkA_last = bkA;
            bkB_last = bkB;
            out[OFF_IDX + (size_t)bA * NSUB + n] = (float)bkA;
            out[OFF_IDX + (size_t)bB * NSUB + n] = (float)bkB;
        }
    }

    // All zero-fills in this block precede the last scan; sync orders them
    // against the single-one writes to the same rows.
    __syncthreads();
    out[OFF_ONEHOT + ((size_t)bA * NSUB + n) * KC + bkA_last] = 1.0f;
    out[OFF_ONEHOT + ((size_t)bB * NSUB + n) * KC + bkB_last] = 1.0f;
}

// ---------------- kernel 3: z_q gather + z_q_out + loss ----------------
__global__ void gather_out_kernel(const float* __restrict__ z,
                                  const float* __restrict__ bias,
                                  float* __restrict__ out) {
    const int b = blockIdx.x;
    const int j = threadIdx.x;
    __shared__ int sidx[48];
    __shared__ float sred[8];

    if (j < 48) sidx[j] = g_idx[(size_t)b * 48 + j];
    __syncthreads();

    float acc = 0.0f;
#pragma unroll
    for (int n = 0; n < NSUB; n++) {
#pragma unroll
        for (int d = 0; d < DEPTHQ; d++) {
            const int k = sidx[n * 3 + d];
            acc += g_P[(((size_t)n << 10) + k) * DIMQ + j];
        }
    }
    const float zq = acc * (1.0f / 3.0f) + bias[j];
    const float zv = z[(size_t)b * DIMQ + j];
    const float diff = zq - zv;
    out[OFF_ZQ + (size_t)b * DIMQ + j] = zv + diff;

    float p = diff * diff;
#pragma unroll
    for (int off = 16; off > 0; off >>= 1) p += __shfl_down_sync(0xffffffffu, p, off);
    if ((j & 31) == 0) sred[j >> 5] = p;
    __syncthreads();
    if (j == 0) {
        float s = 0.0f;
#pragma unroll
        for (int i = 0; i < 8; i++) s += sred[i];
        atomicAdd(out + OFF_LOSS, s * (1.25f / (float)(BQ * DIMQ)));
    }
}

// ---------------- launcher ----------------
extern "C" void kernel_launch(void* const* d_in, const int* in_sizes, int n_in,
                              void* d_out, int out_size) {
    const float* z    = (const float*)d_in[0];
    const float* emb  = (const float*)d_in[1];
    const float* W    = (const float*)d_in[2];
    const float* bias = (const float*)d_in[3];
    float* out = (float*)d_out;

    (void)in_sizes; (void)n_in; (void)out_size;

    // vq first (independent of P) so ncu's sampled launch lands on vq.
    cudaFuncSetAttribute(vq_kernel, cudaFuncAttributeMaxDynamicSharedMemorySize, (int)VQ_SMEM);
    vq_kernel<<<dim3(16, 16), 256, VQ_SMEM>>>(z, emb, out);

    compute_P_kernel<<<1024, 256>>>(emb, W, out);

    gather_out_kernel<<<BQ, 256>>>(z, bias, out);
}

// round 9
// speedup vs baseline: 1.1565x; 1.1565x over previous
#include <cuda_runtime.h>

// Problem constants
#define BQ    8192
#define NSUB  16
#define KC    1024
#define EDIM  16
#define DEPTHQ 3
#define DIMQ  256

// Output layout: [loss(1), z_q_out(B*256), onehot(B*16*1024), idx(B*16)]
#define OFF_LOSS   ((size_t)0)
#define OFF_ZQ     ((size_t)1)
#define OFF_ONEHOT ((size_t)(1 + BQ * DIMQ))
#define OFF_IDX    ((size_t)(OFF_ONEHOT + (size_t)BQ * NSUB * KC))

__device__ float g_P[(size_t)NSUB * KC * DIMQ];
__device__ int   g_idx[(size_t)BQ * NSUB * DEPTHQ];

// ---------------- packed f32x2 helpers ----------------
__device__ __forceinline__ unsigned long long pack2(float a, float b) {
    unsigned long long r;
    asm("mov.b64 %0, {%1,%2};" : "=l"(r) : "f"(a), "f"(b));
    return r;
}
__device__ __forceinline__ void fma2(unsigned long long& d, unsigned long long a, unsigned long long b) {
    asm("fma.rn.f32x2 %0, %1, %2, %0;" : "+l"(d) : "l"(a), "l"(b));
}
__device__ __forceinline__ unsigned long long fma2v(unsigned long long a, unsigned long long b, unsigned long long c) {
    unsigned long long r;
    asm("fma.rn.f32x2 %0, %1, %2, %3;" : "=l"(r) : "l"(a), "l"(b), "l"(c));
    return r;
}
__device__ __forceinline__ unsigned long long add2(unsigned long long a, unsigned long long b) {
    unsigned long long r;
    asm("add.rn.f32x2 %0, %1, %2;" : "=l"(r) : "l"(a), "l"(b));
    return r;
}
__device__ __forceinline__ void unpack2(unsigned long long v, float& lo, float& hi) {
    asm("mov.b64 {%0,%1}, %2;" : "=f"(lo), "=f"(hi) : "l"(v));
}

// ---------------- kernel 1: P precompute (+ zero loss slot) ----------------
__global__ void compute_P_kernel(const float* __restrict__ emb,
                                 const float* __restrict__ W,
                                 float* __restrict__ out) {
    if (blockIdx.x == 0 && threadIdx.x == 0) out[OFF_LOSS] = 0.0f;

    const int n  = blockIdx.x >> 6;
    const int k0 = (blockIdx.x & 63) * 16;
    const int j  = threadIdx.x;

    __shared__ float se[16 * EDIM];
    se[j] = emb[((size_t)n * KC + k0) * EDIM + j];

    float w[16];
#pragma unroll
    for (int i = 0; i < 16; i++) w[i] = W[(size_t)(n * 16 + i) * DIMQ + j];
    __syncthreads();

#pragma unroll
    for (int kk = 0; kk < 16; kk++) {
        float acc = 0.0f;
#pragma unroll
        for (int i = 0; i < 16; i++) acc = fmaf(se[kk * EDIM + i], w[i], acc);
        g_P[((size_t)n * KC + (k0 + kk)) * DIMQ + j] = acc;
    }
}

// ---------------- kernel 2: VQ search — R7 loop, 1 row/thread, 3 blocks/SM ----------------
// grid (32 row-tiles of 256 rows, 16 n), 256 threads, 1 row/thread.
#define NKP (KC / 2)
#define VQ_SMEM ((size_t)(NKP * EDIM * 8 + NKP * 8))

__global__ void __launch_bounds__(256, 3)
vq_kernel(const float* __restrict__ z,
          const float* __restrict__ emb,
          float* __restrict__ out) {
    extern __shared__ unsigned long long sm[];
    unsigned long long* pc = sm;                                 // pc[kp*16 + i] = (e[2kp][i], e[2kp+1][i])
    unsigned long long* s_esq = sm + (size_t)NKP * EDIM;         // (esq[2kp], esq[2kp+1])

    const float* pcf = (const float*)pc;  // e[k][i] at pcf[((k>>1)*16 + i)*2 + (k&1)]

    const int n = blockIdx.y;
    const int rowbase = blockIdx.x * 256;
    const int tid = threadIdx.x;

    // Build paired codebook + esq (sequential fmaf chain per code — matches ref)
    for (int kp = tid; kp < NKP; kp += 256) {
        const float* e0 = emb + ((size_t)n * KC + 2 * kp) * EDIM;
        const float* e1 = e0 + EDIM;
        float esq0 = 0.0f, esq1 = 0.0f;
        unsigned long long* m = pc + (size_t)kp * EDIM;
#pragma unroll
        for (int i = 0; i < 16; i++) {
            float v0 = __ldg(e0 + i);
            float v1 = __ldg(e1 + i);
            esq0 = fmaf(v0, v0, esq0);
            esq1 = fmaf(v1, v1, esq1);
            m[i] = pack2(v0, v1);
        }
        s_esq[kp] = pack2(esq0, esq1);
    }
    __syncthreads();

    // One row per thread.
    const int b = rowbase + tid;
    unsigned long long zd[16];
    unsigned long long zsq2;
    {
        const float* zr = z + (size_t)b * DIMQ + n * EDIM;
        float s = 0.0f;
#pragma unroll
        for (int i = 0; i < 16; i++) {
            float a = zr[i];
            zd[i] = pack2(a, a);
            s = fmaf(a, a, s);
        }
        zsq2 = pack2(s, s);
    }

    const unsigned long long NEG2 = 0xC0000000C0000000ull;  // (-2.f, -2.f)

    int bk_last = 0;

    for (int d = 0; d < DEPTHQ; d++) {
        // Onehot zero-fill, chunk d (indices-independent; overlaps DRAM with scan)
        {
            const int r0 = (d == 0) ? 0 : (86 + (d - 1) * 85);
            const int r1 = (d == 0) ? 86 : (r0 + 85);
            for (int rl = r0; rl < r1; rl++) {
                float* dst = out + OFF_ONEHOT + ((size_t)(rowbase + rl) * NSUB + n) * KC;
                dst[tid]       = 0.0f;
                dst[tid + 256] = 0.0f;
                dst[tid + 512] = 0.0f;
                dst[tid + 768] = 0.0f;
            }
        }

        float bs = 3.4e38f, bd = 3.4e38f;
        int bk = 0;

        // Two kp (= 4 codes) per iteration: 2 independent 16-deep FMA chains
        // per thread; 6 warps/SMSP supply the rest of the latency hiding.
#pragma unroll 1
        for (int kp2 = 0; kp2 < NKP / 2; ++kp2) {
            const ulonglong2* mv0 = (const ulonglong2*)(pc + (size_t)(2 * kp2) * EDIM);
            const ulonglong2* mv1 = mv0 + 8;
            const unsigned long long es0 = s_esq[2 * kp2];
            const unsigned long long es1 = s_esq[2 * kp2 + 1];

            unsigned long long a0 = 0ull, a1 = 0ull;
            // 4 staged sub-chunks (peak m-regs 16). Per chain, sequential
            // i = 0..15 — bit-matches the scalar fmaf chain.
#pragma unroll
            for (int c = 0; c < 4; c++) {
                ulonglong2 p0 = mv0[2 * c], q0 = mv0[2 * c + 1];
                ulonglong2 p1 = mv1[2 * c], q1 = mv1[2 * c + 1];
                const int i = 4 * c;
                fma2(a0, zd[i + 0], p0.x); fma2(a1, zd[i + 0], p1.x);
                fma2(a0, zd[i + 1], p0.y); fma2(a1, zd[i + 1], p1.y);
                fma2(a0, zd[i + 2], q0.x); fma2(a1, zd[i + 2], q1.x);
                fma2(a0, zd[i + 3], q0.y); fma2(a1, zd[i + 3], q1.y);
            }

            // per lane: s = fmaf(-2, c, zsq) + es  (bit-equal to zsq - 2c, then +es)
            unsigned long long s02 = add2(fma2v(a0, NEG2, zsq2), es0);
            unsigned long long s12 = add2(fma2v(a1, NEG2, zsq2), es1);

            float s0, s1, s2, s3;
            unpack2(s02, s0, s1);
            unpack2(s12, s2, s3);

            // Ascending code order: 4kp2, 4kp2+1, 4kp2+2, 4kp2+3.
            const bool c0 = s0 < bs; bs = fminf(bs, s0);
            const bool c1 = s1 < bs; bs = fminf(bs, s1);
            const bool c2 = s2 < bs; bs = fminf(bs, s2);
            const bool c3 = s3 < bs; bs = fminf(bs, s3);

            // Rare path: reference compares d = sqrt(max(s,0)); sqrt can collapse
            // adjacent s -> equal d -> argmin keeps the LOWER index. Updates in
            // strict ascending-k order preserve first-index tie-break exactly.
            if (c0 | c1 | c2 | c3) {
                const int kb = 4 * kp2;
                if (c0) { float dv = sqrtf(fmaxf(s0, 0.0f)); if (dv < bd) { bd = dv; bk = kb; } }
                if (c1) { float dv = sqrtf(fmaxf(s1, 0.0f)); if (dv < bd) { bd = dv; bk = kb + 1; } }
                if (c2) { float dv = sqrtf(fmaxf(s2, 0.0f)); if (dv < bd) { bd = dv; bk = kb + 2; } }
                if (c3) { float dv = sqrtf(fmaxf(s3, 0.0f)); if (dv < bd) { bd = dv; bk = kb + 3; } }
            }
        }

        // Residual update (one fp32 sub per component, matching ref), zsq refresh
        {
            const size_t base = ((size_t)(bk >> 1) * EDIM) * 2 + (bk & 1);
            float s = 0.0f;
#pragma unroll
            for (int i = 0; i < 16; i++) {
                float a, dummy;
                unpack2(zd[i], a, dummy);
                a = a - pcf[base + 2 * i];
                s = fmaf(a, a, s);
                zd[i] = pack2(a, a);
            }
            zsq2 = pack2(s, s);
        }

        g_idx[((size_t)b * NSUB + n) * DEPTHQ + d] = bk;
        if (d == DEPTHQ - 1) {
            bk_last = bk;
            out[OFF_IDX + (size_t)b * NSUB + n] = (float)bk;
        }
    }

    // All zero-fills in this block precede the last scan; sync orders them
    // against the single-one writes to the same rows.
    __syncthreads();
    out[OFF_ONEHOT + ((size_t)b * NSUB + n) * KC + bk_last] = 1.0f;
}

// ---------------- kernel 3: z_q gather + z_q_out + loss ----------------
__global__ void gather_out_kernel(const float* __restrict__ z,
                                  const float* __restrict__ bias,
                                  float* __restrict__ out) {
    const int b = blockIdx.x;
    const int j = threadIdx.x;
    __shared__ int sidx[48];
    __shared__ float sred[8];

    if (j < 48) sidx[j] = g_idx[(size_t)b * 48 + j];
    __syncthreads();

    float acc = 0.0f;
#pragma unroll
    for (int n = 0; n < NSUB; n++) {
#pragma unroll
        for (int d = 0; d < DEPTHQ; d++) {
            const int k = sidx[n * 3 + d];
            acc += g_P[(((size_t)n << 10) + k) * DIMQ + j];
        }
    }
    const float zq = acc * (1.0f / 3.0f) + bias[j];
    const float zv = z[(size_t)b * DIMQ + j];
    const float diff = zq - zv;
    out[OFF_ZQ + (size_t)b * DIMQ + j] = zv + diff;

    float p = diff * diff;
#pragma unroll
    for (int off = 16; off > 0; off >>= 1) p += __shfl_down_sync(0xffffffffu, p, off);
    if ((j & 31) == 0) sred[j >> 5] = p;
    __syncthreads();
    if (j == 0) {
        float s = 0.0f;
#pragma unroll
        for (int i = 0; i < 8; i++) s += sred[i];
        atomicAdd(out + OFF_LOSS, s * (1.25f / (float)(BQ * DIMQ)));
    }
}

// ---------------- launcher ----------------
extern "C" void kernel_launch(void* const* d_in, const int* in_sizes, int n_in,
                              void* d_out, int out_size) {
    const float* z    = (const float*)d_in[0];
    const float* emb  = (const float*)d_in[1];
    const float* W    = (const float*)d_in[2];
    const float* bias = (const float*)d_in[3];
    float* out = (float*)d_out;

    (void)in_sizes; (void)n_in; (void)out_size;

    // vq first (independent of P) so ncu's sampled launch lands on vq.
    cudaFuncSetAttribute(vq_kernel, cudaFuncAttributeMaxDynamicSharedMemorySize, (int)VQ_SMEM);
    vq_kernel<<<dim3(32, 16), 256, VQ_SMEM>>>(z, emb, out);

    compute_P_kernel<<<1024, 256>>>(emb, W, out);

    gather_out_kernel<<<BQ, 256>>>(z, bias, out);
}

// round 10
// speedup vs baseline: 1.2615x; 1.0907x over previous
#include <cuda_runtime.h>

// Problem constants
#define BQ    8192
#define NSUB  16
#define KC    1024
#define EDIM  16
#define DEPTHQ 3
#define DIMQ  256

// Output layout: [loss(1), z_q_out(B*256), onehot(B*16*1024), idx(B*16)]
#define OFF_LOSS   ((size_t)0)
#define OFF_ZQ     ((size_t)1)
#define OFF_ONEHOT ((size_t)(1 + BQ * DIMQ))
#define OFF_IDX    ((size_t)(OFF_ONEHOT + (size_t)BQ * NSUB * KC))

__device__ float g_P[(size_t)NSUB * KC * DIMQ];
__device__ int   g_idx[(size_t)BQ * NSUB * DEPTHQ];

// ---------------- packed f32x2 helpers ----------------
__device__ __forceinline__ unsigned long long pack2(float a, float b) {
    unsigned long long r;
    asm("mov.b64 %0, {%1,%2};" : "=l"(r) : "f"(a), "f"(b));
    return r;
}
__device__ __forceinline__ void fma2(unsigned long long& d, unsigned long long a, unsigned long long b) {
    asm("fma.rn.f32x2 %0, %1, %2, %0;" : "+l"(d) : "l"(a), "l"(b));
}
__device__ __forceinline__ unsigned long long fma2v(unsigned long long a, unsigned long long b, unsigned long long c) {
    unsigned long long r;
    asm("fma.rn.f32x2 %0, %1, %2, %3;" : "=l"(r) : "l"(a), "l"(b), "l"(c));
    return r;
}
__device__ __forceinline__ unsigned long long add2(unsigned long long a, unsigned long long b) {
    unsigned long long r;
    asm("add.rn.f32x2 %0, %1, %2;" : "=l"(r) : "l"(a), "l"(b));
    return r;
}
__device__ __forceinline__ void unpack2(unsigned long long v, float& lo, float& hi) {
    asm("mov.b64 {%0,%1}, %2;" : "=f"(lo), "=f"(hi) : "l"(v));
}

// ---------------- kernel 1: P precompute (+ zero loss slot) ----------------
__global__ void compute_P_kernel(const float* __restrict__ emb,
                                 const float* __restrict__ W,
                                 float* __restrict__ out) {
    if (blockIdx.x == 0 && threadIdx.x == 0) out[OFF_LOSS] = 0.0f;

    const int n  = blockIdx.x >> 6;
    const int k0 = (blockIdx.x & 63) * 16;
    const int j  = threadIdx.x;

    __shared__ float se[16 * EDIM];
    se[j] = emb[((size_t)n * KC + k0) * EDIM + j];

    float w[16];
#pragma unroll
    for (int i = 0; i < 16; i++) w[i] = W[(size_t)(n * 16 + i) * DIMQ + j];
    __syncthreads();

#pragma unroll
    for (int kk = 0; kk < 16; kk++) {
        float acc = 0.0f;
#pragma unroll
        for (int i = 0; i < 16; i++) acc = fmaf(se[kk * EDIM + i], w[i], acc);
        g_P[((size_t)n * KC + (k0 + kk)) * DIMQ + j] = acc;
    }
}

// ---------------- kernel 2: VQ search — R7 loop + double-buffered LDS prefetch ----------------
// grid (16 row-tiles of 512 rows, 16 n), 256 threads, 2 rows/thread, 2 blocks/SM.
#define NKP (KC / 2)
#define VQ_SMEM ((size_t)(NKP * EDIM * 8 + NKP * 8))

// Load chunk c of code-pair group at mvp (pair0 dims 4c..4c+3 in B[0],B[1];
// pair1 same dims in B[2],B[3]).
#define LOADCHUNK(B, mvp, c) \
    B[0] = (mvp)[2*(c)]; B[1] = (mvp)[2*(c)+1]; \
    B[2] = (mvp)[8+2*(c)]; B[3] = (mvp)[8+2*(c)+1];

// Sequential i = 4c..4c+3 per accumulator — bit-matches the scalar fmaf chain.
#define FMACHUNK(B, i) \
    fma2(aA0, zdA[(i)+0], B[0].x); fma2(aB0, zdB[(i)+0], B[0].x); \
    fma2(aA1, zdA[(i)+0], B[2].x); fma2(aB1, zdB[(i)+0], B[2].x); \
    fma2(aA0, zdA[(i)+1], B[0].y); fma2(aB0, zdB[(i)+1], B[0].y); \
    fma2(aA1, zdA[(i)+1], B[2].y); fma2(aB1, zdB[(i)+1], B[2].y); \
    fma2(aA0, zdA[(i)+2], B[1].x); fma2(aB0, zdB[(i)+2], B[1].x); \
    fma2(aA1, zdA[(i)+2], B[3].x); fma2(aB1, zdB[(i)+2], B[3].x); \
    fma2(aA0, zdA[(i)+3], B[1].y); fma2(aB0, zdB[(i)+3], B[1].y); \
    fma2(aA1, zdA[(i)+3], B[3].y); fma2(aB1, zdB[(i)+3], B[3].y);

__global__ void __launch_bounds__(256, 2)
vq_kernel(const float* __restrict__ z,
          const float* __restrict__ emb,
          float* __restrict__ out) {
    extern __shared__ unsigned long long sm[];
    unsigned long long* pc = sm;                                 // pc[kp*16 + i] = (e[2kp][i], e[2kp+1][i])
    unsigned long long* s_esq = sm + (size_t)NKP * EDIM;         // (esq[2kp], esq[2kp+1])

    const float* pcf = (const float*)pc;  // e[k][i] at pcf[((k>>1)*16 + i)*2 + (k&1)]

    const int n = blockIdx.y;
    const int rowbase = blockIdx.x * 512;
    const int tid = threadIdx.x;

    // Build paired codebook + esq (sequential fmaf chain per code — matches ref)
    for (int kp = tid; kp < NKP; kp += 256) {
        const float* e0 = emb + ((size_t)n * KC + 2 * kp) * EDIM;
        const float* e1 = e0 + EDIM;
        float esq0 = 0.0f, esq1 = 0.0f;
        unsigned long long* m = pc + (size_t)kp * EDIM;
#pragma unroll
        for (int i = 0; i < 16; i++) {
            float v0 = __ldg(e0 + i);
            float v1 = __ldg(e1 + i);
            esq0 = fmaf(v0, v0, esq0);
            esq1 = fmaf(v1, v1, esq1);
            m[i] = pack2(v0, v1);
        }
        s_esq[kp] = pack2(esq0, esq1);
    }
    __syncthreads();

    // Two rows per thread: A = rowbase+tid, B = rowbase+256+tid.
    const int bA = rowbase + tid;
    const int bB = rowbase + 256 + tid;
    unsigned long long zdA[16], zdB[16];
    unsigned long long zsqA2, zsqB2;
    {
        const float* zA = z + (size_t)bA * DIMQ + n * EDIM;
        const float* zB = z + (size_t)bB * DIMQ + n * EDIM;
        float sA = 0.0f, sB = 0.0f;
#pragma unroll
        for (int i = 0; i < 16; i++) {
            float a = zA[i], b = zB[i];
            zdA[i] = pack2(a, a);
            zdB[i] = pack2(b, b);
            sA = fmaf(a, a, sA);
            sB = fmaf(b, b, sB);
        }
        zsqA2 = pack2(sA, sA);
        zsqB2 = pack2(sB, sB);
    }

    const unsigned long long NEG2 = 0xC0000000C0000000ull;  // (-2.f, -2.f)

    int bkA_last = 0, bkB_last = 0;

    for (int d = 0; d < DEPTHQ; d++) {
        // Onehot zero-fill, chunk d (indices-independent; overlaps DRAM with scan)
        {
            const int r0 = d * 171;
            const int r1 = (d == 2) ? 512 : (r0 + 171);
            for (int rl = r0; rl < r1; rl++) {
                float* dst = out + OFF_ONEHOT + ((size_t)(rowbase + rl) * NSUB + n) * KC;
                dst[tid]       = 0.0f;
                dst[tid + 256] = 0.0f;
                dst[tid + 512] = 0.0f;
                dst[tid + 768] = 0.0f;
            }
        }

        float bsA = 3.4e38f, bdA = 3.4e38f;
        float bsB = 3.4e38f, bdB = 3.4e38f;
        int bkA = 0, bkB = 0;

        // Double-buffered prefetch: while chunk c computes, chunk c+1 loads.
        // The prefetch of the NEXT kp2's chunk 0 is issued before the rare
        // branch, so its latency hides behind the epilogue too. The final
        // (extra) prefetch lands in the in-bounds esq region and is unused.
        const ulonglong2* mvp = (const ulonglong2*)pc;
        ulonglong2 Ba[4], Bb[4];
        LOADCHUNK(Ba, mvp, 0);

#pragma unroll 1
        for (int kp2 = 0; kp2 < NKP / 2; ++kp2) {
            const unsigned long long es0 = s_esq[2 * kp2];
            const unsigned long long es1 = s_esq[2 * kp2 + 1];
            const ulonglong2* mvn = mvp + 16;

            unsigned long long aA0 = 0ull, aB0 = 0ull, aA1 = 0ull, aB1 = 0ull;

            LOADCHUNK(Bb, mvp, 1);
            FMACHUNK(Ba, 0);
            LOADCHUNK(Ba, mvp, 2);
            FMACHUNK(Bb, 4);
            LOADCHUNK(Bb, mvp, 3);
            FMACHUNK(Ba, 8);
            LOADCHUNK(Ba, mvn, 0);   // prefetch next kp2 (last iter: reads esq region, unused)
            FMACHUNK(Bb, 12);
            mvp = mvn;

            // per lane: s = fmaf(-2, c, zsq) + es  (bit-equal to zsq - 2c, then +es)
            unsigned long long sA02 = add2(fma2v(aA0, NEG2, zsqA2), es0);
            unsigned long long sB02 = add2(fma2v(aB0, NEG2, zsqB2), es0);
            unsigned long long sA12 = add2(fma2v(aA1, NEG2, zsqA2), es1);
            unsigned long long sB12 = add2(fma2v(aB1, NEG2, zsqB2), es1);

            float sA0l, sA0h, sA1l, sA1h, sB0l, sB0h, sB1l, sB1h;
            unpack2(sA02, sA0l, sA0h);
            unpack2(sB02, sB0l, sB0h);
            unpack2(sA12, sA1l, sA1h);
            unpack2(sB12, sB1l, sB1h);

            // Ascending code order: 4kp2, 4kp2+1, 4kp2+2, 4kp2+3.
            const bool cA0l = sA0l < bsA; bsA = fminf(bsA, sA0l);
            const bool cA0h = sA0h < bsA; bsA = fminf(bsA, sA0h);
            const bool cA1l = sA1l < bsA; bsA = fminf(bsA, sA1l);
            const bool cA1h = sA1h < bsA; bsA = fminf(bsA, sA1h);
            const bool cB0l = sB0l < bsB; bsB = fminf(bsB, sB0l);
            const bool cB0h = sB0h < bsB; bsB = fminf(bsB, sB0h);
            const bool cB1l = sB1l < bsB; bsB = fminf(bsB, sB1l);
            const bool cB1h = sB1h < bsB; bsB = fminf(bsB, sB1h);

            // Rare path: reference compares d = sqrt(max(s,0)); sqrt can collapse
            // adjacent s -> equal d -> argmin keeps the LOWER index. Updates in
            // strict ascending-k order preserve first-index tie-break exactly.
            if (cA0l | cA0h | cA1l | cA1h | cB0l | cB0h | cB1l | cB1h) {
                const int kb = 4 * kp2;
                if (cA0l) { float dv = sqrtf(fmaxf(sA0l, 0.0f)); if (dv < bdA) { bdA = dv; bkA = kb; } }
                if (cA0h) { float dv = sqrtf(fmaxf(sA0h, 0.0f)); if (dv < bdA) { bdA = dv; bkA = kb + 1; } }
                if (cA1l) { float dv = sqrtf(fmaxf(sA1l, 0.0f)); if (dv < bdA) { bdA = dv; bkA = kb + 2; } }
                if (cA1h) { float dv = sqrtf(fmaxf(sA1h, 0.0f)); if (dv < bdA) { bdA = dv; bkA = kb + 3; } }
                if (cB0l) { float dv = sqrtf(fmaxf(sB0l, 0.0f)); if (dv < bdB) { bdB = dv; bkB = kb; } }
                if (cB0h) { float dv = sqrtf(fmaxf(sB0h, 0.0f)); if (dv < bdB) { bdB = dv; bkB = kb + 1; } }
                if (cB1l) { float dv = sqrtf(fmaxf(sB1l, 0.0f)); if (dv < bdB) { bdB = dv; bkB = kb + 2; } }
                if (cB1h) { float dv = sqrtf(fmaxf(sB1h, 0.0f)); if (dv < bdB) { bdB = dv; bkB = kb + 3; } }
            }
        }

        // Residual update (one fp32 sub per component, matching ref), zsq refresh
        {
            const size_t baseA = ((size_t)(bkA >> 1) * EDIM) * 2 + (bkA & 1);
            const size_t baseB = ((size_t)(bkB >> 1) * EDIM) * 2 + (bkB & 1);
            float sA = 0.0f, sB = 0.0f;
#pragma unroll
            for (int i = 0; i < 16; i++) {
                float a, dummy, b;
                unpack2(zdA[i], a, dummy);
                unpack2(zdB[i], b, dummy);
                a = a - pcf[baseA + 2 * i];
                b = b - pcf[baseB + 2 * i];
                sA = fmaf(a, a, sA);
                sB = fmaf(b, b, sB);
                zdA[i] = pack2(a, a);
                zdB[i] = pack2(b, b);
            }
            zsqA2 = pack2(sA, sA);
            zsqB2 = pack2(sB, sB);
        }

        g_idx[((size_t)bA * NSUB + n) * DEPTHQ + d] = bkA;
        g_idx[((size_t)bB * NSUB + n) * DEPTHQ + d] = bkB;
        if (d == DEPTHQ - 1) {
            bkA_last = bkA;
            bkB_last = bkB;
            out[OFF_IDX + (size_t)bA * NSUB + n] = (float)bkA;
            out[OFF_IDX + (size_t)bB * NSUB + n] = (float)bkB;
        }
    }

    // All zero-fills in this block precede the last scan; sync orders them
    // against the single-one writes to the same rows.
    __syncthreads();
    out[OFF_ONEHOT + ((size_t)bA * NSUB + n) * KC + bkA_last] = 1.0f;
    out[OFF_ONEHOT + ((size_t)bB * NSUB + n) * KC + bkB_last] = 1.0f;
}

// ---------------- kernel 3: z_q gather + z_q_out + loss ----------------
__global__ void gather_out_kernel(const float* __restrict__ z,
                                  const float* __restrict__ bias,
                                  float* __restrict__ out) {
    const int b = blockIdx.x;
    const int j = threadIdx.x;
    __shared__ int sidx[48];
    __shared__ float sred[8];

    if (j < 48) sidx[j] = g_idx[(size_t)b * 48 + j];
    __syncthreads();

    float acc = 0.0f;
#pragma unroll
    for (int n = 0; n < NSUB; n++) {
#pragma unroll
        for (int d = 0; d < DEPTHQ; d++) {
            const int k = sidx[n * 3 + d];
            acc += g_P[(((size_t)n << 10) + k) * DIMQ + j];
        }
    }
    const float zq = acc * (1.0f / 3.0f) + bias[j];
    const float zv = z[(size_t)b * DIMQ + j];
    const float diff = zq - zv;
    out[OFF_ZQ + (size_t)b * DIMQ + j] = zv + diff;

    float p = diff * diff;
#pragma unroll
    for (int off = 16; off > 0; off >>= 1) p += __shfl_down_sync(0xffffffffu, p, off);
    if ((j & 31) == 0) sred[j >> 5] = p;
    __syncthreads();
    if (j == 0) {
        float s = 0.0f;
#pragma unroll
        for (int i = 0; i < 8; i++) s += sred[i];
        atomicAdd(out + OFF_LOSS, s * (1.25f / (float)(BQ * DIMQ)));
    }
}

// ---------------- launcher ----------------
extern "C" void kernel_launch(void* const* d_in, const int* in_sizes, int n_in,
                              void* d_out, int out_size) {
    const float* z    = (const float*)d_in[0];
    const float* emb  = (const float*)d_in[1];
    const float* W    = (const float*)d_in[2];
    const float* bias = (const float*)d_in[3];
    float* out = (float*)d_out;

    (void)in_sizes; (void)n_in; (void)out_size;

    // vq first (independent of P) so ncu's sampled launch lands on vq.
    cudaFuncSetAttribute(vq_kernel, cudaFuncAttributeMaxDynamicSharedMemorySize, (int)VQ_SMEM);
    vq_kernel<<<dim3(16, 16), 256, VQ_SMEM>>>(z, emb, out);

    compute_P_kernel<<<1024, 256>>>(emb, W, out);

    gather_out_kernel<<<BQ, 256>>>(z, bias, out);
}